// round 1
// baseline (speedup 1.0000x reference)
#include <cuda_runtime.h>
#include <math.h>
#include <stdint.h>

// ---------------------------------------------------------------------------
// MMSSL forward. Shapes (static):
//   U=8192, I=4096, E=64, H=4, IMG_D=4096, TXT_D=1024, LAYERS=1, N_UI=2
// Inputs (metadata order):
//  0 ui_graph[U,I] 1 iu_graph[I,U] 2 image_ui[U,I] 3 image_iu[I,U]
//  4 text_ui[U,I]  5 text_iu[I,U]  6 image_feats[I,4096] 7 text_feats[I,1024]
//  8 W_img[4096,64] 9 b_img[64] 10 W_txt[1024,64] 11 b_txt[64]
// 12 user_id_emb[U,64] 13 item_id_emb[I,64] 14 w_q[64,64] 15 w_k[64,64]
// 16 w_cat[256,64]
// Output: 10 arrays concatenated (4,194,304 floats), see offsets below.
// ---------------------------------------------------------------------------

#define UDIM 8192
#define IDIM 4096

static constexpr float MODEL_CAT = 0.55f;
static constexpr float ID_CAT    = 0.36f;

// output offsets (floats)
static constexpr size_t OFF_UG_A  = 0;        // u_g (copy 1)     [U,64]
static constexpr size_t OFF_IG_A  = 524288;   // i_g (copy 1)     [I,64]
static constexpr size_t OFF_IIF   = 786432;   // image_item_feats [I,64]
static constexpr size_t OFF_TIF   = 1048576;  // text_item_feats  [I,64]
static constexpr size_t OFF_IUF   = 1310720;  // image_user_feats [U,64]
static constexpr size_t OFF_TUF   = 1835008;  // text_user_feats  [U,64]
static constexpr size_t OFF_UG_B  = 2359296;  // u_g (copy 2)     [U,64]
static constexpr size_t OFF_IG_B  = 2883584;  // i_g (copy 2)     [I,64]
static constexpr size_t OFF_IUID  = 3145728;  // image_user_id    [U,64]
static constexpr size_t OFF_TUID  = 3670016;  // text_user_id     [U,64]

// scratch layout (floats). Atomic-accumulated buffers first (must be zeroed).
static constexpr size_t S_IMGF  = 0;         // img_f            [I,64]
static constexpr size_t S_TXTF  = 262144;    // txt_f            [I,64]
static constexpr size_t S_IIID  = 524288;    // image_item_id    [I,64]
static constexpr size_t S_TIID  = 786432;    // text_item_id     [I,64]
static constexpr size_t S_UG1   = 1048576;   // u_g1             [U,64]
static constexpr size_t S_UG2   = 1572864;   // u_g2             [U,64]
static constexpr size_t S_IG1   = 2097152;   // i_g1             [I,64]
static constexpr size_t S_IG2   = 2359296;   // i_g2             [I,64]
static constexpr size_t S_ZERO_END = 2621440; // end of atomic targets
static constexpr size_t S_UG0   = 2621440;   // u_g0 (MHSA out)  [U,64]
static constexpr size_t S_IG0   = 3145728;   // i_g0 (MHSA out)  [I,64]
static constexpr size_t S_TOTAL = 3407872;

__device__ float g_scratch[S_TOTAL];

// ---------------------------------------------------------------------------
// Generic skinny SGEMM: C[M,N] (+)= A[M,K] @ B[K,N], N in {64,128}.
// Split-K across grid.y (chunk 1024), fp32 atomicAdd epilogue.
// N=128 supports split B (two [K,64] operands) and split C (two [M,64] outs).
// ---------------------------------------------------------------------------

struct Job {
    const float* A;
    const float* B1;
    const float* B2;
    const float* bias;
    float* C1;
    float* C2;
    int M;
    int K;
};
struct Jobs4 { Job j[4]; };

static constexpr int BM = 128;
static constexpr int BK = 16;
static constexpr int KCHUNK = 1024;

template<int BN>
__global__ __launch_bounds__(256) void gemm_kernel(Jobs4 P)
{
    constexpr int TN = BN / 16;   // 4 (BN=64) or 8 (BN=128)
    Job jb = P.j[blockIdx.z];
    const int mb = blockIdx.x * BM;
    if (mb >= jb.M) return;
    const int kc = blockIdx.y * KCHUNK;
    if (kc >= jb.K) return;

    __shared__ float As[BK][BM];
    __shared__ float Bs[BK][BN];

    const int tid = threadIdx.x;
    const int tx = tid & 15;       // 16 col-groups
    const int ty = tid >> 4;       // 16 row-groups (8 rows each)

    float acc[8][TN];
#pragma unroll
    for (int r = 0; r < 8; r++)
#pragma unroll
        for (int c = 0; c < TN; c++) acc[r][c] = 0.f;

    const float* Abase = jb.A + (size_t)mb * jb.K;
    const int K = jb.K;

    for (int k0 = kc; k0 < kc + KCHUNK; k0 += BK) {
        // --- load A tile (128x16) transposed into As[k][row] ---
#pragma unroll
        for (int i = 0; i < 2; i++) {
            int f = tid + i * 256;             // 512 float4s
            int row = f >> 2;
            int c4  = (f & 3) * 4;
            float4 v = *reinterpret_cast<const float4*>(
                Abase + (size_t)row * K + k0 + c4);
            As[c4 + 0][row] = v.x;
            As[c4 + 1][row] = v.y;
            As[c4 + 2][row] = v.z;
            As[c4 + 3][row] = v.w;
        }
        // --- load B tile (16xBN) ---
        if constexpr (BN == 64) {
            int r = tid >> 4;
            int c = (tid & 15) * 4;
            *reinterpret_cast<float4*>(&Bs[r][c]) =
                *reinterpret_cast<const float4*>(jb.B1 + (size_t)(k0 + r) * 64 + c);
        } else {
#pragma unroll
            for (int i = 0; i < 2; i++) {
                int f = tid + i * 256;         // 512 float4s
                int r = f >> 5;
                int c = (f & 31) * 4;
                const float* src = (c < 64)
                    ? (jb.B1 + (size_t)(k0 + r) * 64 + c)
                    : (jb.B2 + (size_t)(k0 + r) * 64 + (c - 64));
                *reinterpret_cast<float4*>(&Bs[r][c]) =
                    *reinterpret_cast<const float4*>(src);
            }
        }
        __syncthreads();

#pragma unroll
        for (int k = 0; k < BK; k++) {
            float ar[8];
            float4 a0 = *reinterpret_cast<const float4*>(&As[k][ty * 8]);
            float4 a1 = *reinterpret_cast<const float4*>(&As[k][ty * 8 + 4]);
            ar[0]=a0.x; ar[1]=a0.y; ar[2]=a0.z; ar[3]=a0.w;
            ar[4]=a1.x; ar[5]=a1.y; ar[6]=a1.z; ar[7]=a1.w;
            float br[TN];
            if constexpr (BN == 64) {
                float4 b0 = *reinterpret_cast<const float4*>(&Bs[k][tx * 4]);
                br[0]=b0.x; br[1]=b0.y; br[2]=b0.z; br[3]=b0.w;
            } else {
                float4 b0 = *reinterpret_cast<const float4*>(&Bs[k][tx * 8]);
                float4 b1 = *reinterpret_cast<const float4*>(&Bs[k][tx * 8 + 4]);
                br[0]=b0.x; br[1]=b0.y; br[2]=b0.z; br[3]=b0.w;
                br[4]=b1.x; br[5]=b1.y; br[6]=b1.z; br[7]=b1.w;
            }
#pragma unroll
            for (int r = 0; r < 8; r++)
#pragma unroll
                for (int c = 0; c < TN; c++)
                    acc[r][c] = fmaf(ar[r], br[c], acc[r][c]);
        }
        __syncthreads();
    }

    const bool addb = (blockIdx.y == 0) && (jb.bias != nullptr);
#pragma unroll
    for (int r = 0; r < 8; r++) {
        int row = mb + ty * 8 + r;
#pragma unroll
        for (int c = 0; c < TN; c++) {
            int col = tx * TN + c;
            float v = acc[r][c];
            if (addb) v += jb.bias[col];
            if constexpr (BN == 64) {
                atomicAdd(jb.C1 + (size_t)row * 64 + col, v);
            } else {
                if (col < 64) atomicAdd(jb.C1 + (size_t)row * 64 + col, v);
                else          atomicAdd(jb.C2 + (size_t)row * 64 + (col - 64), v);
            }
        }
    }
}

// ---------------------------------------------------------------------------
// MHSA over the 2-modality axis, fused with mean / row-norm / id-emb add:
//   out[n] = idemb[n] + ID_CAT * rownorm( mean_a( Z_a[n] @ w_cat ) )
// One warp per row; lane handles columns (lane, lane+32).
// ---------------------------------------------------------------------------
__global__ __launch_bounds__(256) void mhsa_kernel(
    const float* __restrict__ xi, const float* __restrict__ xt,
    const float* __restrict__ idemb,
    const float* __restrict__ wq, const float* __restrict__ wk,
    const float* __restrict__ wcat,
    float* __restrict__ outp, int M)
{
    __shared__ float sx[8][2][64];
    __shared__ float sqk[8][4][64];   // qi, ki, qt, kt
    __shared__ float satt[8][16];
    const int warp = threadIdx.x >> 5;
    const int lane = threadIdx.x & 31;
    const int gw = blockIdx.x * 8 + warp;
    const int nw = gridDim.x * 8;

    for (int n = gw; n < M; n += nw) {
        sx[warp][0][lane]      = xi[(size_t)n * 64 + lane];
        sx[warp][0][lane + 32] = xi[(size_t)n * 64 + lane + 32];
        sx[warp][1][lane]      = xt[(size_t)n * 64 + lane];
        sx[warp][1][lane + 32] = xt[(size_t)n * 64 + lane + 32];
        __syncwarp();

        float qi0=0,qi1=0,ki0=0,ki1=0,qt0=0,qt1=0,kt0=0,kt1=0;
        float pi[4][2] = {}, pt[4][2] = {};
#pragma unroll 4
        for (int k = 0; k < 64; k++) {
            float xik = sx[warp][0][k];
            float xtk = sx[warp][1][k];
            float wq0 = wq[k * 64 + lane],      wq1 = wq[k * 64 + lane + 32];
            float wk0 = wk[k * 64 + lane],      wk1 = wk[k * 64 + lane + 32];
            qi0 = fmaf(xik, wq0, qi0); qi1 = fmaf(xik, wq1, qi1);
            ki0 = fmaf(xik, wk0, ki0); ki1 = fmaf(xik, wk1, ki1);
            qt0 = fmaf(xtk, wq0, qt0); qt1 = fmaf(xtk, wq1, qt1);
            kt0 = fmaf(xtk, wk0, kt0); kt1 = fmaf(xtk, wk1, kt1);
#pragma unroll
            for (int h = 0; h < 4; h++) {
                float wc0 = wcat[(h * 64 + k) * 64 + lane];
                float wc1 = wcat[(h * 64 + k) * 64 + lane + 32];
                pi[h][0] = fmaf(xik, wc0, pi[h][0]);
                pi[h][1] = fmaf(xik, wc1, pi[h][1]);
                pt[h][0] = fmaf(xtk, wc0, pt[h][0]);
                pt[h][1] = fmaf(xtk, wc1, pt[h][1]);
            }
        }
        sqk[warp][0][lane] = qi0; sqk[warp][0][lane + 32] = qi1;
        sqk[warp][1][lane] = ki0; sqk[warp][1][lane + 32] = ki1;
        sqk[warp][2][lane] = qt0; sqk[warp][2][lane + 32] = qt1;
        sqk[warp][3][lane] = kt0; sqk[warp][3][lane + 32] = kt1;
        __syncwarp();

        // 16 attention logits: c = h*4 + a*2 + b; softmax over b (pairs).
        {
            int cc = lane & 15;
            int h = cc >> 2, a = (cc >> 1) & 1, b = cc & 1;
            const float* qv = &sqk[warp][a * 2][h * 16];
            const float* kv = &sqk[warp][1 + b * 2][h * 16];
            float l = 0.f;
#pragma unroll
            for (int u = 0; u < 16; u++) l = fmaf(qv[u], kv[u], l);
            l *= 0.25f;   // 1/sqrt(dh=16)
            float lo = __shfl_xor_sync(0xffffffffu, l, 1);
            float mm = fmaxf(l, lo);
            float e  = expf(l - mm);
            float eo = __shfl_xor_sync(0xffffffffu, e, 1);
            float att = e / (e + eo);
            if (lane < 16) satt[warp][lane] = att;
        }
        __syncwarp();

        // zmean = sum_h ci[h]*pi[h] + ct[h]*pt[h] (0.5 = modality mean)
        float z0 = 0.f, z1 = 0.f;
#pragma unroll
        for (int h = 0; h < 4; h++) {
            float cih = 0.5f * (satt[warp][h * 4 + 0] + satt[warp][h * 4 + 2]);
            float cth = 0.5f * (satt[warp][h * 4 + 1] + satt[warp][h * 4 + 3]);
            z0 = fmaf(cih, pi[h][0], fmaf(cth, pt[h][0], z0));
            z1 = fmaf(cih, pi[h][1], fmaf(cth, pt[h][1], z1));
        }
        float ss = z0 * z0 + z1 * z1;
#pragma unroll
        for (int o = 16; o; o >>= 1) ss += __shfl_xor_sync(0xffffffffu, ss, o);
        float scale = ID_CAT / fmaxf(sqrtf(ss), 1e-12f);
        outp[(size_t)n * 64 + lane]      = idemb[(size_t)n * 64 + lane]      + z0 * scale;
        outp[(size_t)n * 64 + lane + 32] = idemb[(size_t)n * 64 + lane + 32] + z1 * scale;
        __syncwarp();
    }
}

// row softmax over 64 columns, in place; one warp per row
__global__ __launch_bounds__(256) void softmax_kernel(float* __restrict__ X, int M)
{
    const int warp = threadIdx.x >> 5;
    const int lane = threadIdx.x & 31;
    const int gw = blockIdx.x * 8 + warp;
    const int nw = gridDim.x * 8;
    for (int n = gw; n < M; n += nw) {
        size_t i = (size_t)n * 64 + lane;
        float v0 = X[i], v1 = X[i + 32];
        float m = fmaxf(v0, v1);
#pragma unroll
        for (int o = 16; o; o >>= 1) m = fmaxf(m, __shfl_xor_sync(0xffffffffu, m, o));
        float e0 = expf(v0 - m), e1 = expf(v1 - m);
        float s = e0 + e1;
#pragma unroll
        for (int o = 16; o; o >>= 1) s += __shfl_xor_sync(0xffffffffu, s, o);
        float inv = 1.0f / s;
        X[i] = e0 * inv;
        X[i + 32] = e1 * inv;
    }
}

// out = mean(g0,g1,g2) + 0.55*rownorm(fA) + 0.55*rownorm(fB) -> o1 and o2
__global__ __launch_bounds__(256) void epilogue_kernel(
    const float* __restrict__ g0, const float* __restrict__ g1,
    const float* __restrict__ g2,
    const float* __restrict__ fA, const float* __restrict__ fB,
    float* __restrict__ o1, float* __restrict__ o2, int M)
{
    const int warp = threadIdx.x >> 5;
    const int lane = threadIdx.x & 31;
    const int gw = blockIdx.x * 8 + warp;
    const int nw = gridDim.x * 8;
    for (int n = gw; n < M; n += nw) {
        size_t i = (size_t)n * 64 + lane;
        size_t i2 = i + 32;
        float m0 = (g0[i]  + g1[i]  + g2[i])  * (1.0f / 3.0f);
        float m1 = (g0[i2] + g1[i2] + g2[i2]) * (1.0f / 3.0f);
        float a0 = fA[i], a1 = fA[i2];
        float ssa = a0 * a0 + a1 * a1;
#pragma unroll
        for (int o = 16; o; o >>= 1) ssa += __shfl_xor_sync(0xffffffffu, ssa, o);
        float sA = MODEL_CAT / fmaxf(sqrtf(ssa), 1e-12f);
        float b0 = fB[i], b1 = fB[i2];
        float ssb = b0 * b0 + b1 * b1;
#pragma unroll
        for (int o = 16; o; o >>= 1) ssb += __shfl_xor_sync(0xffffffffu, ssb, o);
        float sB = MODEL_CAT / fmaxf(sqrtf(ssb), 1e-12f);
        float r0 = m0 + a0 * sA + b0 * sB;
        float r1 = m1 + a1 * sA + b1 * sB;
        o1[i] = r0;  o1[i2] = r1;
        o2[i] = r0;  o2[i2] = r1;
    }
}

// ---------------------------------------------------------------------------
extern "C" void kernel_launch(void* const* d_in, const int* in_sizes, int n_in,
                              void* d_out, int out_size)
{
    const float* ui      = (const float*)d_in[0];
    const float* iu      = (const float*)d_in[1];
    const float* img_ui  = (const float*)d_in[2];
    const float* img_iu  = (const float*)d_in[3];
    const float* txt_ui  = (const float*)d_in[4];
    const float* txt_iu  = (const float*)d_in[5];
    const float* imgF    = (const float*)d_in[6];
    const float* txtF    = (const float*)d_in[7];
    const float* W_img   = (const float*)d_in[8];
    const float* b_img   = (const float*)d_in[9];
    const float* W_txt   = (const float*)d_in[10];
    const float* b_txt   = (const float*)d_in[11];
    const float* uid     = (const float*)d_in[12];
    const float* iid     = (const float*)d_in[13];
    const float* w_q     = (const float*)d_in[14];
    const float* w_k     = (const float*)d_in[15];
    const float* w_cat   = (const float*)d_in[16];
    float* out = (float*)d_out;

    float* scr = nullptr;
    cudaGetSymbolAddress((void**)&scr, g_scratch);

    float* s_imgf = scr + S_IMGF;
    float* s_txtf = scr + S_TXTF;
    float* s_iiid = scr + S_IIID;
    float* s_tiid = scr + S_TIID;
    float* s_ug1  = scr + S_UG1;
    float* s_ug2  = scr + S_UG2;
    float* s_ig1  = scr + S_IG1;
    float* s_ig2  = scr + S_IG2;
    float* s_ug0  = scr + S_UG0;
    float* s_ig0  = scr + S_IG0;

    // zero all atomic-accumulation targets (d_out is poisoned)
    cudaMemsetAsync(out, 0, (size_t)4194304 * sizeof(float));
    cudaMemsetAsync(scr, 0, S_ZERO_END * sizeof(float));

    Jobs4 P;

    // L1: img_f = image_feats@W_img + b_img ; txt_f = text_feats@W_txt + b_txt
    P = Jobs4{};
    P.j[0] = Job{imgF, W_img, nullptr, b_img, s_imgf, nullptr, IDIM, 4096};
    P.j[1] = Job{txtF, W_txt, nullptr, b_txt, s_txtf, nullptr, IDIM, 1024};
    gemm_kernel<64><<<dim3(IDIM / BM, 4, 2), 256>>>(P);

    // L2: [imageUF | textUF] = ui_graph @ [img_f | txt_f]
    P = Jobs4{};
    P.j[0] = Job{ui, s_imgf, s_txtf, nullptr, out + OFF_IUF, out + OFF_TUF, UDIM, 4096};
    gemm_kernel<128><<<dim3(UDIM / BM, 4, 1), 256>>>(P);

    // L3: [imageIF | textIF] = iu_graph @ [imageUF | textUF]
    P = Jobs4{};
    P.j[0] = Job{iu, out + OFF_IUF, out + OFF_TUF, nullptr, out + OFF_IIF, out + OFF_TIF, IDIM, 8192};
    gemm_kernel<128><<<dim3(IDIM / BM, 8, 1), 256>>>(P);

    // L4: 4 id propagations
    P = Jobs4{};
    P.j[0] = Job{img_ui, iid, nullptr, nullptr, out + OFF_IUID, nullptr, UDIM, 4096};
    P.j[1] = Job{txt_ui, iid, nullptr, nullptr, out + OFF_TUID, nullptr, UDIM, 4096};
    P.j[2] = Job{img_iu, uid, nullptr, nullptr, s_iiid, nullptr, IDIM, 8192};
    P.j[3] = Job{txt_iu, uid, nullptr, nullptr, s_tiid, nullptr, IDIM, 8192};
    gemm_kernel<64><<<dim3(UDIM / BM, 8, 4), 256>>>(P);

    // L5/L6: MHSA (modality attention) -> u_g0, i_g0
    mhsa_kernel<<<1024, 256>>>(out + OFF_IUID, out + OFF_TUID, uid, w_q, w_k, w_cat, s_ug0, UDIM);
    mhsa_kernel<<<512, 256>>>(s_iiid, s_tiid, iid, w_q, w_k, w_cat, s_ig0, IDIM);

    // propagation loop (N_UI = 2)
    P = Jobs4{};
    P.j[0] = Job{ui, s_ig0, nullptr, nullptr, s_ug1, nullptr, UDIM, 4096};
    gemm_kernel<64><<<dim3(UDIM / BM, 4, 1), 256>>>(P);

    P = Jobs4{};
    P.j[0] = Job{iu, s_ug1, nullptr, nullptr, s_ig1, nullptr, IDIM, 8192};
    gemm_kernel<64><<<dim3(IDIM / BM, 8, 1), 256>>>(P);

    P = Jobs4{};
    P.j[0] = Job{ui, s_ig1, nullptr, nullptr, s_ug2, nullptr, UDIM, 4096};
    gemm_kernel<64><<<dim3(UDIM / BM, 4, 1), 256>>>(P);
    softmax_kernel<<<1024, 256>>>(s_ug2, UDIM);

    P = Jobs4{};
    P.j[0] = Job{iu, s_ug2, nullptr, nullptr, s_ig2, nullptr, IDIM, 8192};
    gemm_kernel<64><<<dim3(IDIM / BM, 8, 1), 256>>>(P);
    softmax_kernel<<<512, 256>>>(s_ig2, IDIM);

    // final combine -> u_g (out0, out6), i_g (out1, out7)
    epilogue_kernel<<<1024, 256>>>(s_ug0, s_ug1, s_ug2,
                                   out + OFF_IUF, out + OFF_TUF,
                                   out + OFF_UG_A, out + OFF_UG_B, UDIM);
    epilogue_kernel<<<512, 256>>>(s_ig0, s_ig1, s_ig2,
                                  out + OFF_IIF, out + OFF_TIF,
                                  out + OFF_IG_A, out + OFF_IG_B, IDIM);
}

// round 3
// speedup vs baseline: 1.8539x; 1.8539x over previous
#include <cuda_runtime.h>
#include <math.h>
#include <stdint.h>

// ===========================================================================
// MMSSL forward — tf32 mma.sync edition (portable sm_80+ tensor path; the
// harness's compute_103 virtual arch rejects tcgen05).
// U=8192, I=4096, E=64. All heavy GEMMs: C[M,64] += A[M,K] @ B[K,64] with
// block 128x64x32, warp tile 32x32 (m16n8k8 tf32), split-K + fp32 atomics.
// Both operands RNA-rounded to tf32 on the STS path (unbiased).
// ===========================================================================

#define UDIM 8192
#define IDIM 4096

static constexpr float MODEL_CAT = 0.55f;
static constexpr float ID_CAT    = 0.36f;

// ---- output offsets (floats) ----
static constexpr size_t OFF_UG_A  = 0;
static constexpr size_t OFF_IG_A  = 524288;
static constexpr size_t OFF_IIF   = 786432;
static constexpr size_t OFF_TIF   = 1048576;
static constexpr size_t OFF_IUF   = 1310720;
static constexpr size_t OFF_TUF   = 1835008;
static constexpr size_t OFF_UG_B  = 2359296;
static constexpr size_t OFF_IG_B  = 2883584;
static constexpr size_t OFF_IUID  = 3145728;
static constexpr size_t OFF_TUID  = 3670016;

// ---- scratch (floats); [0, S_ZERO_END) is atomic-accumulated, zeroed ----
static constexpr size_t S_IMGF  = 0;
static constexpr size_t S_TXTF  = 262144;
static constexpr size_t S_IIID  = 524288;
static constexpr size_t S_TIID  = 786432;
static constexpr size_t S_UG1   = 1048576;
static constexpr size_t S_UG2   = 1572864;
static constexpr size_t S_IG1   = 2097152;
static constexpr size_t S_IG2   = 2359296;
static constexpr size_t S_ZERO_END = 2621440;
static constexpr size_t S_UG0   = 2621440;
static constexpr size_t S_IG0   = 3145728;
static constexpr size_t S_TOTAL = 3407872;

__device__ float g_scratch[S_TOTAL];

// ===========================================================================
__device__ __forceinline__ float rna_tf32(float x) {
    float r;
    asm("cvt.rna.tf32.f32 %0, %1;" : "=f"(r) : "f"(x));
    return r;
}

__device__ __forceinline__ void mma8(float* d,
                                     uint32_t a0, uint32_t a1, uint32_t a2, uint32_t a3,
                                     uint32_t b0, uint32_t b1) {
    asm volatile(
        "mma.sync.aligned.m16n8k8.row.col.f32.tf32.tf32.f32 "
        "{%0,%1,%2,%3}, {%4,%5,%6,%7}, {%8,%9}, {%0,%1,%2,%3};\n"
        : "+f"(d[0]), "+f"(d[1]), "+f"(d[2]), "+f"(d[3])
        : "r"(a0), "r"(a1), "r"(a2), "r"(a3), "r"(b0), "r"(b1));
}

// ===========================================================================
// GEMM: C[M,64] += A[M,K] @ B[K,64]
//   grid = (M/128, splits, n_jobs); chunk = K/gridDim.y (multiple of 32)
//   SMEM A: paired-k float2, K-major: As2[p][row], p=(k/8)*4+(k%4),
//           pair=(k,k+4), row stride 132 f2  -> conflict-free frag LDS.64
//   SMEM B: K-major Bs[k][col], row stride 72 floats -> conflict-free LDS.32
// ===========================================================================
struct GJob {
    const float* A;
    const float* B;
    const float* bias;
    float* C;
    int M;
    int K;
};
struct GJobs2 { GJob j[2]; };

static constexpr uint32_t A_BUF = 16u * 132u * 8u;   // 16896 B
static constexpr uint32_t B_BUF = 32u * 72u * 4u;    // 9216 B
static constexpr uint32_t SM_BOFF = 2u * A_BUF;      // 33792
static constexpr uint32_t GEMM_SMEM = SM_BOFF + 2u * B_BUF;  // 52224

__global__ __launch_bounds__(256) void gemm_mma(GJobs2 P)
{
    extern __shared__ char sm[];
    const GJob jb = P.j[blockIdx.z];
    const int mb = blockIdx.x * 128;
    if (mb >= jb.M) return;
    const int K = jb.K;
    const int chunk = K / gridDim.y;
    const int k0 = blockIdx.y * chunk;
    const int nt = chunk >> 5;

    const int tid  = threadIdx.x;
    const int lane = tid & 31;
    const int wid  = tid >> 5;
    const int gid  = lane >> 2;
    const int tig  = lane & 3;
    const int wm   = (wid & 3) * 32;
    const int wn   = (wid >> 2) * 32;

    // LDG mapping
    const int ar  = tid >> 1;              // A row 0..127
    const int akc = (tid & 1) * 16;        // A k sub-offset
    const float* __restrict__ Ap = jb.A + (size_t)(mb + ar) * K + k0 + akc;
    const int bk  = tid >> 4;              // B k row (first half)
    const int bc4 = (tid & 15) * 4;        // B col
    const float* __restrict__ Bp = jb.B + (size_t)(k0 + bk) * 64 + bc4;

    float acc[2][4][4];
#pragma unroll
    for (int m = 0; m < 2; m++)
#pragma unroll
        for (int j = 0; j < 4; j++)
#pragma unroll
            for (int c = 0; c < 4; c++) acc[m][j][c] = 0.f;

    float4 av[4], bv[2];

    auto LDGA = [&](int t) {
        const float* p = Ap + t * 32;
#pragma unroll
        for (int i = 0; i < 4; i++)
            av[i] = *reinterpret_cast<const float4*>(p + 4 * i);
        const float* q = Bp + (size_t)t * 32 * 64;
        bv[0] = *reinterpret_cast<const float4*>(q);
        bv[1] = *reinterpret_cast<const float4*>(q + 16 * 64);
    };

    auto STS = [&](int b) {
        char* ab = sm + (uint32_t)b * A_BUF;
#pragma unroll
        for (int i = 0; i < 2; i++) {          // i -> av[2i] paired with av[2i+1]
            const float* lo = &av[2 * i].x;
            const float* hi = &av[2 * i + 1].x;
#pragma unroll
            for (int j = 0; j < 4; j++) {
                int k = akc + 8 * i + j;       // k%8 = j (<4)
                int p = (k >> 3) * 4 + j;
                float2 v = make_float2(rna_tf32(lo[j]), rna_tf32(hi[j]));
                *reinterpret_cast<float2*>(ab + ((p * 132 + ar) << 3)) = v;
            }
        }
        char* bb = sm + SM_BOFF + (uint32_t)b * B_BUF;
        float4 r0, r1;
        r0.x = rna_tf32(bv[0].x); r0.y = rna_tf32(bv[0].y);
        r0.z = rna_tf32(bv[0].z); r0.w = rna_tf32(bv[0].w);
        r1.x = rna_tf32(bv[1].x); r1.y = rna_tf32(bv[1].y);
        r1.z = rna_tf32(bv[1].z); r1.w = rna_tf32(bv[1].w);
        *reinterpret_cast<float4*>(bb + (size_t)(bk * 72 + bc4) * 4) = r0;
        *reinterpret_cast<float4*>(bb + (size_t)((bk + 16) * 72 + bc4) * 4) = r1;
    };

    auto COMP = [&](int b) {
        const char* ab = sm + (uint32_t)b * A_BUF;
        const char* bb = sm + SM_BOFF + (uint32_t)b * B_BUF;
#pragma unroll
        for (int ks = 0; ks < 4; ks++) {
            uint32_t a0[2], a1[2], a2[2], a3[2];
            const int p = ks * 4 + tig;
#pragma unroll
            for (int mt = 0; mt < 2; mt++) {
                int row = wm + mt * 16 + gid;
                float2 lo = *reinterpret_cast<const float2*>(ab + ((p * 132 + row) << 3));
                float2 hi = *reinterpret_cast<const float2*>(ab + ((p * 132 + row + 8) << 3));
                a0[mt] = __float_as_uint(lo.x);
                a2[mt] = __float_as_uint(lo.y);
                a1[mt] = __float_as_uint(hi.x);
                a3[mt] = __float_as_uint(hi.y);
            }
#pragma unroll
            for (int j = 0; j < 4; j++) {
                int col = wn + j * 8 + gid;
                uint32_t b0 = __float_as_uint(
                    *reinterpret_cast<const float*>(bb + (size_t)((ks * 8 + tig) * 72 + col) * 4));
                uint32_t b1 = __float_as_uint(
                    *reinterpret_cast<const float*>(bb + (size_t)((ks * 8 + tig + 4) * 72 + col) * 4));
#pragma unroll
                for (int mt = 0; mt < 2; mt++)
                    mma8(acc[mt][j], a0[mt], a1[mt], a2[mt], a3[mt], b0, b1);
            }
        }
    };

    LDGA(0);
    STS(0);
    __syncthreads();
    for (int t = 0; t < nt; t++) {
        if (t + 1 < nt) LDGA(t + 1);
        COMP(t & 1);
        if (t + 1 < nt) STS((t + 1) & 1);
        __syncthreads();
    }

    const bool addb = (blockIdx.y == 0) && (jb.bias != nullptr);
#pragma unroll
    for (int mt = 0; mt < 2; mt++) {
#pragma unroll
        for (int j = 0; j < 4; j++) {
            int row = mb + wm + mt * 16 + gid;
            int col = wn + j * 8 + 2 * tig;
            float b0 = addb ? jb.bias[col] : 0.f;
            float b1 = addb ? jb.bias[col + 1] : 0.f;
            atomicAdd(jb.C + (size_t)row * 64 + col,           acc[mt][j][0] + b0);
            atomicAdd(jb.C + (size_t)row * 64 + col + 1,       acc[mt][j][1] + b1);
            atomicAdd(jb.C + (size_t)(row + 8) * 64 + col,     acc[mt][j][2] + b0);
            atomicAdd(jb.C + (size_t)(row + 8) * 64 + col + 1, acc[mt][j][3] + b1);
        }
    }
}

// ===========================================================================
// MHSA over the 2-modality axis fused with mean/norm/id-add
// ===========================================================================
__global__ __launch_bounds__(256) void mhsa_kernel(
    const float* __restrict__ xi, const float* __restrict__ xt,
    const float* __restrict__ idemb,
    const float* __restrict__ wq, const float* __restrict__ wk,
    const float* __restrict__ wcat,
    float* __restrict__ outp, int M)
{
    __shared__ float sx[8][2][64];
    __shared__ float sqk[8][4][64];
    __shared__ float satt[8][16];
    const int warp = threadIdx.x >> 5;
    const int lane = threadIdx.x & 31;
    const int gw = blockIdx.x * 8 + warp;
    const int nw = gridDim.x * 8;

    for (int n = gw; n < M; n += nw) {
        sx[warp][0][lane]      = xi[(size_t)n * 64 + lane];
        sx[warp][0][lane + 32] = xi[(size_t)n * 64 + lane + 32];
        sx[warp][1][lane]      = xt[(size_t)n * 64 + lane];
        sx[warp][1][lane + 32] = xt[(size_t)n * 64 + lane + 32];
        __syncwarp();

        float qi0=0,qi1=0,ki0=0,ki1=0,qt0=0,qt1=0,kt0=0,kt1=0;
        float pi[4][2] = {}, pt[4][2] = {};
#pragma unroll 4
        for (int k = 0; k < 64; k++) {
            float xik = sx[warp][0][k];
            float xtk = sx[warp][1][k];
            float wq0 = wq[k * 64 + lane],      wq1 = wq[k * 64 + lane + 32];
            float wk0 = wk[k * 64 + lane],      wk1 = wk[k * 64 + lane + 32];
            qi0 = fmaf(xik, wq0, qi0); qi1 = fmaf(xik, wq1, qi1);
            ki0 = fmaf(xik, wk0, ki0); ki1 = fmaf(xik, wk1, ki1);
            qt0 = fmaf(xtk, wq0, qt0); qt1 = fmaf(xtk, wq1, qt1);
            kt0 = fmaf(xtk, wk0, kt0); kt1 = fmaf(xtk, wk1, kt1);
#pragma unroll
            for (int h = 0; h < 4; h++) {
                float wc0 = wcat[(h * 64 + k) * 64 + lane];
                float wc1 = wcat[(h * 64 + k) * 64 + lane + 32];
                pi[h][0] = fmaf(xik, wc0, pi[h][0]);
                pi[h][1] = fmaf(xik, wc1, pi[h][1]);
                pt[h][0] = fmaf(xtk, wc0, pt[h][0]);
                pt[h][1] = fmaf(xtk, wc1, pt[h][1]);
            }
        }
        sqk[warp][0][lane] = qi0; sqk[warp][0][lane + 32] = qi1;
        sqk[warp][1][lane] = ki0; sqk[warp][1][lane + 32] = ki1;
        sqk[warp][2][lane] = qt0; sqk[warp][2][lane + 32] = qt1;
        sqk[warp][3][lane] = kt0; sqk[warp][3][lane + 32] = kt1;
        __syncwarp();

        {
            int cc = lane & 15;
            int h = cc >> 2, a = (cc >> 1) & 1, b = cc & 1;
            const float* qv = &sqk[warp][a * 2][h * 16];
            const float* kv = &sqk[warp][1 + b * 2][h * 16];
            float l = 0.f;
#pragma unroll
            for (int u = 0; u < 16; u++) l = fmaf(qv[u], kv[u], l);
            l *= 0.25f;
            float lo = __shfl_xor_sync(0xffffffffu, l, 1);
            float mm = fmaxf(l, lo);
            float e  = expf(l - mm);
            float eo = __shfl_xor_sync(0xffffffffu, e, 1);
            float att = e / (e + eo);
            if (lane < 16) satt[warp][lane] = att;
        }
        __syncwarp();

        float z0 = 0.f, z1 = 0.f;
#pragma unroll
        for (int h = 0; h < 4; h++) {
            float cih = 0.5f * (satt[warp][h * 4 + 0] + satt[warp][h * 4 + 2]);
            float cth = 0.5f * (satt[warp][h * 4 + 1] + satt[warp][h * 4 + 3]);
            z0 = fmaf(cih, pi[h][0], fmaf(cth, pt[h][0], z0));
            z1 = fmaf(cih, pi[h][1], fmaf(cth, pt[h][1], z1));
        }
        float ss = z0 * z0 + z1 * z1;
#pragma unroll
        for (int o = 16; o; o >>= 1) ss += __shfl_xor_sync(0xffffffffu, ss, o);
        float scale = ID_CAT / fmaxf(sqrtf(ss), 1e-12f);
        outp[(size_t)n * 64 + lane]      = idemb[(size_t)n * 64 + lane]      + z0 * scale;
        outp[(size_t)n * 64 + lane + 32] = idemb[(size_t)n * 64 + lane + 32] + z1 * scale;
        __syncwarp();
    }
}

__global__ __launch_bounds__(256) void softmax_kernel(float* __restrict__ X, int M)
{
    const int warp = threadIdx.x >> 5;
    const int lane = threadIdx.x & 31;
    const int gw = blockIdx.x * 8 + warp;
    const int nw = gridDim.x * 8;
    for (int n = gw; n < M; n += nw) {
        size_t i = (size_t)n * 64 + lane;
        float v0 = X[i], v1 = X[i + 32];
        float m = fmaxf(v0, v1);
#pragma unroll
        for (int o = 16; o; o >>= 1) m = fmaxf(m, __shfl_xor_sync(0xffffffffu, m, o));
        float e0 = expf(v0 - m), e1 = expf(v1 - m);
        float s = e0 + e1;
#pragma unroll
        for (int o = 16; o; o >>= 1) s += __shfl_xor_sync(0xffffffffu, s, o);
        float inv = 1.0f / s;
        X[i] = e0 * inv;
        X[i + 32] = e1 * inv;
    }
}

__global__ __launch_bounds__(256) void epilogue_kernel(
    const float* __restrict__ g0, const float* __restrict__ g1,
    const float* __restrict__ g2,
    const float* __restrict__ fA, const float* __restrict__ fB,
    float* __restrict__ o1, float* __restrict__ o2, int M)
{
    const int warp = threadIdx.x >> 5;
    const int lane = threadIdx.x & 31;
    const int gw = blockIdx.x * 8 + warp;
    const int nw = gridDim.x * 8;
    for (int n = gw; n < M; n += nw) {
        size_t i = (size_t)n * 64 + lane;
        size_t i2 = i + 32;
        float m0 = (g0[i]  + g1[i]  + g2[i])  * (1.0f / 3.0f);
        float m1 = (g0[i2] + g1[i2] + g2[i2]) * (1.0f / 3.0f);
        float a0 = fA[i], a1 = fA[i2];
        float ssa = a0 * a0 + a1 * a1;
#pragma unroll
        for (int o = 16; o; o >>= 1) ssa += __shfl_xor_sync(0xffffffffu, ssa, o);
        float sA = MODEL_CAT / fmaxf(sqrtf(ssa), 1e-12f);
        float b0 = fB[i], b1 = fB[i2];
        float ssb = b0 * b0 + b1 * b1;
#pragma unroll
        for (int o = 16; o; o >>= 1) ssb += __shfl_xor_sync(0xffffffffu, ssb, o);
        float sB = MODEL_CAT / fmaxf(sqrtf(ssb), 1e-12f);
        float r0 = m0 + a0 * sA + b0 * sB;
        float r1 = m1 + a1 * sA + b1 * sB;
        o1[i] = r0;  o1[i2] = r1;
        o2[i] = r0;  o2[i2] = r1;
    }
}

// ===========================================================================
extern "C" void kernel_launch(void* const* d_in, const int* in_sizes, int n_in,
                              void* d_out, int out_size)
{
    const float* ui      = (const float*)d_in[0];
    const float* iu      = (const float*)d_in[1];
    const float* img_ui  = (const float*)d_in[2];
    const float* img_iu  = (const float*)d_in[3];
    const float* txt_ui  = (const float*)d_in[4];
    const float* txt_iu  = (const float*)d_in[5];
    const float* imgF    = (const float*)d_in[6];
    const float* txtF    = (const float*)d_in[7];
    const float* W_img   = (const float*)d_in[8];
    const float* b_img   = (const float*)d_in[9];
    const float* W_txt   = (const float*)d_in[10];
    const float* b_txt   = (const float*)d_in[11];
    const float* uid     = (const float*)d_in[12];
    const float* iid     = (const float*)d_in[13];
    const float* w_q     = (const float*)d_in[14];
    const float* w_k     = (const float*)d_in[15];
    const float* w_cat   = (const float*)d_in[16];
    float* out = (float*)d_out;

    float* scr = nullptr;
    cudaGetSymbolAddress((void**)&scr, g_scratch);

    cudaFuncSetAttribute(gemm_mma, cudaFuncAttributeMaxDynamicSharedMemorySize,
                         (int)GEMM_SMEM);

    // zero all atomic-accumulation targets (d_out is poisoned)
    cudaMemsetAsync(out, 0, (size_t)4194304 * sizeof(float));
    cudaMemsetAsync(scr, 0, S_ZERO_END * sizeof(float));

    GJobs2 P;

    // G1: feature projections (bias)
    P.j[0] = GJob{imgF, W_img, b_img, scr + S_IMGF, IDIM, 4096};
    P.j[1] = GJob{txtF, W_txt, b_txt, scr + S_TXTF, IDIM, 1024};
    gemm_mma<<<dim3(32, 8, 2), 256, GEMM_SMEM>>>(P);

    // G4a/G4b: id propagations (independent of features)
    P.j[0] = GJob{img_ui, iid, nullptr, out + OFF_IUID, UDIM, 4096};
    P.j[1] = GJob{txt_ui, iid, nullptr, out + OFF_TUID, UDIM, 4096};
    gemm_mma<<<dim3(64, 4, 2), 256, GEMM_SMEM>>>(P);
    P.j[0] = GJob{img_iu, uid, nullptr, scr + S_IIID, IDIM, 8192};
    P.j[1] = GJob{txt_iu, uid, nullptr, scr + S_TIID, IDIM, 8192};
    gemm_mma<<<dim3(32, 8, 2), 256, GEMM_SMEM>>>(P);

    // G2: imageUF = ui@img_f ; textUF = ui@txt_f
    P.j[0] = GJob{ui, scr + S_IMGF, nullptr, out + OFF_IUF, UDIM, 4096};
    P.j[1] = GJob{ui, scr + S_TXTF, nullptr, out + OFF_TUF, UDIM, 4096};
    gemm_mma<<<dim3(64, 4, 2), 256, GEMM_SMEM>>>(P);

    // G3: imageIF = iu@imageUF ; textIF = iu@textUF
    P.j[0] = GJob{iu, out + OFF_IUF, nullptr, out + OFF_IIF, IDIM, 8192};
    P.j[1] = GJob{iu, out + OFF_TUF, nullptr, out + OFF_TIF, IDIM, 8192};
    gemm_mma<<<dim3(32, 8, 2), 256, GEMM_SMEM>>>(P);

    // MHSA (modality attention) -> u_g0, i_g0
    mhsa_kernel<<<1024, 256>>>(out + OFF_IUID, out + OFF_TUID, uid,
                               w_q, w_k, w_cat, scr + S_UG0, UDIM);
    mhsa_kernel<<<512, 256>>>(scr + S_IIID, scr + S_TIID, iid,
                              w_q, w_k, w_cat, scr + S_IG0, IDIM);

    // propagation loop (N_UI = 2)
    P.j[0] = GJob{ui, scr + S_IG0, nullptr, scr + S_UG1, UDIM, 4096};
    P.j[1] = P.j[0];
    gemm_mma<<<dim3(64, 8, 1), 256, GEMM_SMEM>>>(P);

    P.j[0] = GJob{iu, scr + S_UG1, nullptr, scr + S_IG1, IDIM, 8192};
    P.j[1] = P.j[0];
    gemm_mma<<<dim3(32, 16, 1), 256, GEMM_SMEM>>>(P);

    P.j[0] = GJob{ui, scr + S_IG1, nullptr, scr + S_UG2, UDIM, 4096};
    P.j[1] = P.j[0];
    gemm_mma<<<dim3(64, 8, 1), 256, GEMM_SMEM>>>(P);
    softmax_kernel<<<1024, 256>>>(scr + S_UG2, UDIM);

    P.j[0] = GJob{iu, scr + S_UG2, nullptr, scr + S_IG2, IDIM, 8192};
    P.j[1] = P.j[0];
    gemm_mma<<<dim3(32, 16, 1), 256, GEMM_SMEM>>>(P);
    softmax_kernel<<<512, 256>>>(scr + S_IG2, IDIM);

    // final combine
    epilogue_kernel<<<1024, 256>>>(scr + S_UG0, scr + S_UG1, scr + S_UG2,
                                   out + OFF_IUF, out + OFF_TUF,
                                   out + OFF_UG_A, out + OFF_UG_B, UDIM);
    epilogue_kernel<<<512, 256>>>(scr + S_IG0, scr + S_IG1, scr + S_IG2,
                                  out + OFF_IIF, out + OFF_TIF,
                                  out + OFF_IG_A, out + OFF_IG_B, IDIM);
}

// round 4
// speedup vs baseline: 2.7717x; 1.4950x over previous
#include <cuda_runtime.h>
#include <math.h>
#include <stdint.h>

// ===========================================================================
// MMSSL forward — tf32 mma.sync + cp.async pipeline.
// Block 128x64x32 (128 threads, 4 warps, warp tile 64x32), 2-stage cp.async,
// 4 CTAs/SM. B operands pre-rounded (RNA) to tf32 in GMEM; A rounded on the
// fragment-load path. Split-K + fp32 atomicAdd epilogue.
// ===========================================================================

#define UDIM 8192
#define IDIM 4096

static constexpr float MODEL_CAT = 0.55f;
static constexpr float ID_CAT    = 0.36f;

// ---- output offsets (floats) ----
static constexpr size_t OFF_UG_A  = 0;
static constexpr size_t OFF_IG_A  = 524288;
static constexpr size_t OFF_IIF   = 786432;
static constexpr size_t OFF_TIF   = 1048576;
static constexpr size_t OFF_IUF   = 1310720;
static constexpr size_t OFF_TUF   = 1835008;
static constexpr size_t OFF_UG_B  = 2359296;
static constexpr size_t OFF_IG_B  = 2883584;
static constexpr size_t OFF_IUID  = 3145728;
static constexpr size_t OFF_TUID  = 3670016;

// ---- scratch (floats); [0, S_ZERO_END) is atomic-accumulated, zeroed ----
static constexpr size_t S_IMGF  = 0;
static constexpr size_t S_TXTF  = 262144;
static constexpr size_t S_IIID  = 524288;
static constexpr size_t S_TIID  = 786432;
static constexpr size_t S_UG1   = 1048576;
static constexpr size_t S_UG2   = 1572864;
static constexpr size_t S_IG1   = 2097152;
static constexpr size_t S_IG2   = 2359296;
static constexpr size_t S_ZERO_END = 2621440;
static constexpr size_t S_UG0   = 2621440;
static constexpr size_t S_IG0   = 3145728;   // (unrounded i_g0 for epilogue)
// rounded-B buffers
static constexpr size_t S_RWIMG = 3407872;   // 262144
static constexpr size_t S_RWTXT = 3670016;   // 65536
static constexpr size_t S_RIID  = 3735552;   // 262144
static constexpr size_t S_RUID  = 3997696;   // 524288
static constexpr size_t S_RB3   = 4521984;   // 2x524288 (IUF_r | TUF_r)
static constexpr size_t S_RIG0  = 5570560;   // 262144
static constexpr size_t S_RUG1  = 5832704;   // 524288
static constexpr size_t S_RIG1  = 6356992;   // 262144
static constexpr size_t S_RUG2  = 6881280;   // 524288
static constexpr size_t S_TOTAL = 7405568;

__device__ float g_scratch[S_TOTAL];

// ===========================================================================
__device__ __forceinline__ float rna_tf32(float x) {
    float r;
    asm("cvt.rna.tf32.f32 %0, %1;" : "=f"(r) : "f"(x));
    return r;
}
__device__ __forceinline__ uint32_t s2u(const void* p) {
    uint32_t a;
    asm("{ .reg .u64 t; cvta.to.shared.u64 t, %1; cvt.u32.u64 %0, t; }"
        : "=r"(a) : "l"(p));
    return a;
}
__device__ __forceinline__ void cp16(uint32_t s, const void* g) {
    asm volatile("cp.async.cg.shared.global [%0], [%1], 16;"
                 :: "r"(s), "l"(g) : "memory");
}
__device__ __forceinline__ float lds_f(uint32_t a) {
    float v;
    asm volatile("ld.shared.f32 %0, [%1];" : "=f"(v) : "r"(a));
    return v;
}
__device__ __forceinline__ void mma8(float* d,
                                     uint32_t a0, uint32_t a1, uint32_t a2, uint32_t a3,
                                     uint32_t b0, uint32_t b1) {
    asm volatile(
        "mma.sync.aligned.m16n8k8.row.col.f32.tf32.tf32.f32 "
        "{%0,%1,%2,%3}, {%4,%5,%6,%7}, {%8,%9}, {%0,%1,%2,%3};\n"
        : "+f"(d[0]), "+f"(d[1]), "+f"(d[2]), "+f"(d[3])
        : "r"(a0), "r"(a1), "r"(a2), "r"(a3), "r"(b0), "r"(b1));
}

// ===========================================================================
// GEMM: C[M,64] += rna(A[M,K]) @ B_r[K,64]   (B pre-rounded in gmem)
// smem: A stage [128][36] f32 (rows 144B), B stage [32][72] f32 (rows 288B)
// ===========================================================================
struct GJob {
    const float* A;
    const float* B;
    const float* bias;
    float* C;
    int M;
    int K;
};
struct GJobs2 { GJob j[2]; };

static constexpr uint32_t ABUF_B  = 128u * 144u;          // 18432
static constexpr uint32_t BBUF_B  = 32u * 288u;           // 9216
static constexpr uint32_t STAGE_B = ABUF_B + BBUF_B;      // 27648
static constexpr uint32_t GEMM_SMEM = 2u * STAGE_B;       // 55296

__global__ __launch_bounds__(128, 4) void gemm_cp(GJobs2 P)
{
    extern __shared__ char sm[];
    const GJob jb = P.j[blockIdx.z];
    const int mb = blockIdx.x * 128;
    if (mb >= jb.M) return;
    const int K = jb.K;
    const int chunk = K / (int)gridDim.y;
    const int k0 = (int)blockIdx.y * chunk;
    const int nt = chunk >> 5;

    const int tid  = threadIdx.x;
    const int lane = tid & 31;
    const int wid  = tid >> 5;
    const int gid  = lane >> 2;
    const int tig  = lane & 3;
    const int wm   = (wid & 1) * 64;
    const int wn   = (wid >> 1) * 32;

    const uint32_t sb = s2u(sm);
    const float* __restrict__ Ag = jb.A + (size_t)mb * K + k0;
    const float* __restrict__ Bg = jb.B + (size_t)k0 * 64;

    float acc[4][4][4];
#pragma unroll
    for (int m = 0; m < 4; m++)
#pragma unroll
        for (int j = 0; j < 4; j++)
#pragma unroll
            for (int c = 0; c < 4; c++) acc[m][j][c] = 0.f;

    auto LOAD = [&](int t, int buf) {
        const uint32_t ab = sb + (uint32_t)buf * STAGE_B;
        const uint32_t bb = ab + ABUF_B;
        const float* At = Ag + t * 32;
        const float* Bt = Bg + (size_t)t * 32 * 64;
#pragma unroll
        for (int i = 0; i < 8; i++) {
            int c = i * 128 + tid;
            int row = c >> 3, seg = c & 7;
            cp16(ab + (uint32_t)(row * 144 + seg * 16),
                 At + (size_t)row * K + seg * 4);
        }
#pragma unroll
        for (int i = 0; i < 4; i++) {
            int c = i * 128 + tid;
            int k = c >> 4, seg = c & 15;
            cp16(bb + (uint32_t)(k * 288 + seg * 16),
                 Bt + (size_t)k * 64 + seg * 4);
        }
        asm volatile("cp.async.commit_group;" ::: "memory");
    };

    auto COMP = [&](int buf) {
        const uint32_t ab = sb + (uint32_t)buf * STAGE_B;
        const uint32_t bb = ab + ABUF_B;
#pragma unroll
        for (int ks = 0; ks < 4; ks++) {
            uint32_t a0[4], a1[4], a2[4], a3[4];
            const int k = ks * 8 + tig;
#pragma unroll
            for (int mt = 0; mt < 4; mt++) {
                int row = wm + mt * 16 + gid;
                float x0 = lds_f(ab + (uint32_t)((row * 36 + k) << 2));
                float x1 = lds_f(ab + (uint32_t)(((row + 8) * 36 + k) << 2));
                float x2 = lds_f(ab + (uint32_t)((row * 36 + k + 4) << 2));
                float x3 = lds_f(ab + (uint32_t)(((row + 8) * 36 + k + 4) << 2));
                a0[mt] = __float_as_uint(rna_tf32(x0));
                a1[mt] = __float_as_uint(rna_tf32(x1));
                a2[mt] = __float_as_uint(rna_tf32(x2));
                a3[mt] = __float_as_uint(rna_tf32(x3));
            }
#pragma unroll
            for (int j = 0; j < 4; j++) {
                int col = wn + j * 8 + gid;
                uint32_t b0 = __float_as_uint(
                    lds_f(bb + (uint32_t)(((ks * 8 + tig) * 72 + col) << 2)));
                uint32_t b1 = __float_as_uint(
                    lds_f(bb + (uint32_t)(((ks * 8 + tig + 4) * 72 + col) << 2)));
#pragma unroll
                for (int mt = 0; mt < 4; mt++)
                    mma8(acc[mt][j], a0[mt], a1[mt], a2[mt], a3[mt], b0, b1);
            }
        }
    };

    LOAD(0, 0);
    for (int t = 0; t < nt; t++) {
        const int buf = t & 1;
        if (t + 1 < nt) {
            LOAD(t + 1, buf ^ 1);
            asm volatile("cp.async.wait_group 1;" ::: "memory");
        } else {
            asm volatile("cp.async.wait_group 0;" ::: "memory");
        }
        __syncthreads();
        COMP(buf);
        __syncthreads();
    }

    const bool addb = (blockIdx.y == 0) && (jb.bias != nullptr);
#pragma unroll
    for (int mt = 0; mt < 4; mt++) {
#pragma unroll
        for (int j = 0; j < 4; j++) {
            int row = mb + wm + mt * 16 + gid;
            int col = wn + j * 8 + 2 * tig;
            float b0 = addb ? jb.bias[col] : 0.f;
            float b1 = addb ? jb.bias[col + 1] : 0.f;
            atomicAdd(jb.C + (size_t)row * 64 + col,           acc[mt][j][0] + b0);
            atomicAdd(jb.C + (size_t)row * 64 + col + 1,       acc[mt][j][1] + b1);
            atomicAdd(jb.C + (size_t)(row + 8) * 64 + col,     acc[mt][j][2] + b0);
            atomicAdd(jb.C + (size_t)(row + 8) * 64 + col + 1, acc[mt][j][3] + b1);
        }
    }
}

// ===========================================================================
// elementwise RNA round (copy or in-place)
// ===========================================================================
__global__ __launch_bounds__(256) void round_copy(
    const float* __restrict__ src, float* __restrict__ dst, int n)
{
    int i = blockIdx.x * 256 + threadIdx.x;
    int stride = gridDim.x * 256;
    for (; i < n; i += stride) dst[i] = rna_tf32(src[i]);
}

// ===========================================================================
// MHSA over the 2-modality axis fused with mean/norm/id-add.
// Optional outr: rounded copy of the result (for downstream B use).
// ===========================================================================
__global__ __launch_bounds__(256) void mhsa_kernel(
    const float* __restrict__ xi, const float* __restrict__ xt,
    const float* __restrict__ idemb,
    const float* __restrict__ wq, const float* __restrict__ wk,
    const float* __restrict__ wcat,
    float* __restrict__ outp, float* __restrict__ outr, int M)
{
    __shared__ float sx[8][2][64];
    __shared__ float sqk[8][4][64];
    __shared__ float satt[8][16];
    const int warp = threadIdx.x >> 5;
    const int lane = threadIdx.x & 31;
    const int gw = blockIdx.x * 8 + warp;
    const int nw = gridDim.x * 8;

    for (int n = gw; n < M; n += nw) {
        sx[warp][0][lane]      = xi[(size_t)n * 64 + lane];
        sx[warp][0][lane + 32] = xi[(size_t)n * 64 + lane + 32];
        sx[warp][1][lane]      = xt[(size_t)n * 64 + lane];
        sx[warp][1][lane + 32] = xt[(size_t)n * 64 + lane + 32];
        __syncwarp();

        float qi0=0,qi1=0,ki0=0,ki1=0,qt0=0,qt1=0,kt0=0,kt1=0;
        float pi[4][2] = {}, pt[4][2] = {};
#pragma unroll 4
        for (int k = 0; k < 64; k++) {
            float xik = sx[warp][0][k];
            float xtk = sx[warp][1][k];
            float wq0 = wq[k * 64 + lane],      wq1 = wq[k * 64 + lane + 32];
            float wk0 = wk[k * 64 + lane],      wk1 = wk[k * 64 + lane + 32];
            qi0 = fmaf(xik, wq0, qi0); qi1 = fmaf(xik, wq1, qi1);
            ki0 = fmaf(xik, wk0, ki0); ki1 = fmaf(xik, wk1, ki1);
            qt0 = fmaf(xtk, wq0, qt0); qt1 = fmaf(xtk, wq1, qt1);
            kt0 = fmaf(xtk, wk0, kt0); kt1 = fmaf(xtk, wk1, kt1);
#pragma unroll
            for (int h = 0; h < 4; h++) {
                float wc0 = wcat[(h * 64 + k) * 64 + lane];
                float wc1 = wcat[(h * 64 + k) * 64 + lane + 32];
                pi[h][0] = fmaf(xik, wc0, pi[h][0]);
                pi[h][1] = fmaf(xik, wc1, pi[h][1]);
                pt[h][0] = fmaf(xtk, wc0, pt[h][0]);
                pt[h][1] = fmaf(xtk, wc1, pt[h][1]);
            }
        }
        sqk[warp][0][lane] = qi0; sqk[warp][0][lane + 32] = qi1;
        sqk[warp][1][lane] = ki0; sqk[warp][1][lane + 32] = ki1;
        sqk[warp][2][lane] = qt0; sqk[warp][2][lane + 32] = qt1;
        sqk[warp][3][lane] = kt0; sqk[warp][3][lane + 32] = kt1;
        __syncwarp();

        {
            int cc = lane & 15;
            int h = cc >> 2, a = (cc >> 1) & 1, b = cc & 1;
            const float* qv = &sqk[warp][a * 2][h * 16];
            const float* kv = &sqk[warp][1 + b * 2][h * 16];
            float l = 0.f;
#pragma unroll
            for (int u = 0; u < 16; u++) l = fmaf(qv[u], kv[u], l);
            l *= 0.25f;
            float lo = __shfl_xor_sync(0xffffffffu, l, 1);
            float mm = fmaxf(l, lo);
            float e  = expf(l - mm);
            float eo = __shfl_xor_sync(0xffffffffu, e, 1);
            float att = e / (e + eo);
            if (lane < 16) satt[warp][lane] = att;
        }
        __syncwarp();

        float z0 = 0.f, z1 = 0.f;
#pragma unroll
        for (int h = 0; h < 4; h++) {
            float cih = 0.5f * (satt[warp][h * 4 + 0] + satt[warp][h * 4 + 2]);
            float cth = 0.5f * (satt[warp][h * 4 + 1] + satt[warp][h * 4 + 3]);
            z0 = fmaf(cih, pi[h][0], fmaf(cth, pt[h][0], z0));
            z1 = fmaf(cih, pi[h][1], fmaf(cth, pt[h][1], z1));
        }
        float ss = z0 * z0 + z1 * z1;
#pragma unroll
        for (int o = 16; o; o >>= 1) ss += __shfl_xor_sync(0xffffffffu, ss, o);
        float scale = ID_CAT / fmaxf(sqrtf(ss), 1e-12f);
        float r0 = idemb[(size_t)n * 64 + lane]      + z0 * scale;
        float r1 = idemb[(size_t)n * 64 + lane + 32] + z1 * scale;
        outp[(size_t)n * 64 + lane]      = r0;
        outp[(size_t)n * 64 + lane + 32] = r1;
        if (outr) {
            outr[(size_t)n * 64 + lane]      = rna_tf32(r0);
            outr[(size_t)n * 64 + lane + 32] = rna_tf32(r1);
        }
        __syncwarp();
    }
}

// row softmax; optional rounded copy
__global__ __launch_bounds__(256) void softmax_kernel(
    float* __restrict__ X, float* __restrict__ outr, int M)
{
    const int warp = threadIdx.x >> 5;
    const int lane = threadIdx.x & 31;
    const int gw = blockIdx.x * 8 + warp;
    const int nw = gridDim.x * 8;
    for (int n = gw; n < M; n += nw) {
        size_t i = (size_t)n * 64 + lane;
        float v0 = X[i], v1 = X[i + 32];
        float m = fmaxf(v0, v1);
#pragma unroll
        for (int o = 16; o; o >>= 1) m = fmaxf(m, __shfl_xor_sync(0xffffffffu, m, o));
        float e0 = expf(v0 - m), e1 = expf(v1 - m);
        float s = e0 + e1;
#pragma unroll
        for (int o = 16; o; o >>= 1) s += __shfl_xor_sync(0xffffffffu, s, o);
        float inv = 1.0f / s;
        float r0 = e0 * inv, r1 = e1 * inv;
        X[i] = r0;
        X[i + 32] = r1;
        if (outr) {
            outr[i] = rna_tf32(r0);
            outr[i + 32] = rna_tf32(r1);
        }
    }
}

__global__ __launch_bounds__(256) void epilogue_kernel(
    const float* __restrict__ g0, const float* __restrict__ g1,
    const float* __restrict__ g2,
    const float* __restrict__ fA, const float* __restrict__ fB,
    float* __restrict__ o1, float* __restrict__ o2, int M)
{
    const int warp = threadIdx.x >> 5;
    const int lane = threadIdx.x & 31;
    const int gw = blockIdx.x * 8 + warp;
    const int nw = gridDim.x * 8;
    for (int n = gw; n < M; n += nw) {
        size_t i = (size_t)n * 64 + lane;
        size_t i2 = i + 32;
        float m0 = (g0[i]  + g1[i]  + g2[i])  * (1.0f / 3.0f);
        float m1 = (g0[i2] + g1[i2] + g2[i2]) * (1.0f / 3.0f);
        float a0 = fA[i], a1 = fA[i2];
        float ssa = a0 * a0 + a1 * a1;
#pragma unroll
        for (int o = 16; o; o >>= 1) ssa += __shfl_xor_sync(0xffffffffu, ssa, o);
        float sA = MODEL_CAT / fmaxf(sqrtf(ssa), 1e-12f);
        float b0 = fB[i], b1 = fB[i2];
        float ssb = b0 * b0 + b1 * b1;
#pragma unroll
        for (int o = 16; o; o >>= 1) ssb += __shfl_xor_sync(0xffffffffu, ssb, o);
        float sB = MODEL_CAT / fmaxf(sqrtf(ssb), 1e-12f);
        float r0 = m0 + a0 * sA + b0 * sB;
        float r1 = m1 + a1 * sA + b1 * sB;
        o1[i] = r0;  o1[i2] = r1;
        o2[i] = r0;  o2[i2] = r1;
    }
}

// ===========================================================================
extern "C" void kernel_launch(void* const* d_in, const int* in_sizes, int n_in,
                              void* d_out, int out_size)
{
    const float* ui      = (const float*)d_in[0];
    const float* iu      = (const float*)d_in[1];
    const float* img_ui  = (const float*)d_in[2];
    const float* img_iu  = (const float*)d_in[3];
    const float* txt_ui  = (const float*)d_in[4];
    const float* txt_iu  = (const float*)d_in[5];
    const float* imgF    = (const float*)d_in[6];
    const float* txtF    = (const float*)d_in[7];
    const float* W_img   = (const float*)d_in[8];
    const float* b_img   = (const float*)d_in[9];
    const float* W_txt   = (const float*)d_in[10];
    const float* b_txt   = (const float*)d_in[11];
    const float* uid     = (const float*)d_in[12];
    const float* iid     = (const float*)d_in[13];
    const float* w_q     = (const float*)d_in[14];
    const float* w_k     = (const float*)d_in[15];
    const float* w_cat   = (const float*)d_in[16];
    float* out = (float*)d_out;

    float* scr = nullptr;
    cudaGetSymbolAddress((void**)&scr, g_scratch);

    cudaFuncSetAttribute(gemm_cp, cudaFuncAttributeMaxDynamicSharedMemorySize,
                         (int)GEMM_SMEM);

    // zero atomic-accumulation targets (d_out is poisoned)
    cudaMemsetAsync(out, 0, (size_t)4194304 * sizeof(float));
    cudaMemsetAsync(scr, 0, S_ZERO_END * sizeof(float));

    // prep: round static B operands
    round_copy<<<256, 256>>>(W_img, scr + S_RWIMG, 262144);
    round_copy<<<64, 256>>>(W_txt, scr + S_RWTXT, 65536);
    round_copy<<<256, 256>>>(iid,  scr + S_RIID,  262144);
    round_copy<<<512, 256>>>(uid,  scr + S_RUID,  524288);

    GJobs2 P;

    // G1: feature projections (bias)
    P.j[0] = GJob{imgF, scr + S_RWIMG, b_img, scr + S_IMGF, IDIM, 4096};
    P.j[1] = GJob{txtF, scr + S_RWTXT, b_txt, scr + S_TXTF, IDIM, 1024};
    gemm_cp<<<dim3(32, 8, 2), 128, GEMM_SMEM>>>(P);

    // G4a/G4b: id propagations
    P.j[0] = GJob{img_ui, scr + S_RIID, nullptr, out + OFF_IUID, UDIM, 4096};
    P.j[1] = GJob{txt_ui, scr + S_RIID, nullptr, out + OFF_TUID, UDIM, 4096};
    gemm_cp<<<dim3(64, 4, 2), 128, GEMM_SMEM>>>(P);
    P.j[0] = GJob{img_iu, scr + S_RUID, nullptr, scr + S_IIID, IDIM, 8192};
    P.j[1] = GJob{txt_iu, scr + S_RUID, nullptr, scr + S_TIID, IDIM, 8192};
    gemm_cp<<<dim3(32, 8, 2), 128, GEMM_SMEM>>>(P);

    // round img_f|txt_f in place (contiguous, only consumed as B afterwards)
    round_copy<<<512, 256>>>(scr + S_IMGF, scr + S_IMGF, 524288);

    // G2: imageUF = ui@img_f ; textUF = ui@txt_f
    P.j[0] = GJob{ui, scr + S_IMGF, nullptr, out + OFF_IUF, UDIM, 4096};
    P.j[1] = GJob{ui, scr + S_TXTF, nullptr, out + OFF_TUF, UDIM, 4096};
    gemm_cp<<<dim3(64, 4, 2), 128, GEMM_SMEM>>>(P);

    // rounded copies of UF for G3's B
    round_copy<<<512, 256>>>(out + OFF_IUF, scr + S_RB3, 524288);
    round_copy<<<512, 256>>>(out + OFF_TUF, scr + S_RB3 + 524288, 524288);

    // G3: imageIF = iu@imageUF ; textIF = iu@textUF
    P.j[0] = GJob{iu, scr + S_RB3, nullptr, out + OFF_IIF, IDIM, 8192};
    P.j[1] = GJob{iu, scr + S_RB3 + 524288, nullptr, out + OFF_TIF, IDIM, 8192};
    gemm_cp<<<dim3(32, 8, 2), 128, GEMM_SMEM>>>(P);

    // MHSA -> u_g0, i_g0 (i_g0 also emitted rounded for loop1 B)
    mhsa_kernel<<<1024, 256>>>(out + OFF_IUID, out + OFF_TUID, uid,
                               w_q, w_k, w_cat, scr + S_UG0, nullptr, UDIM);
    mhsa_kernel<<<512, 256>>>(scr + S_IIID, scr + S_TIID, iid,
                              w_q, w_k, w_cat, scr + S_IG0, scr + S_RIG0, IDIM);

    // propagation loop (N_UI = 2)
    P.j[0] = GJob{ui, scr + S_RIG0, nullptr, scr + S_UG1, UDIM, 4096};
    P.j[1] = P.j[0];
    gemm_cp<<<dim3(64, 8, 1), 128, GEMM_SMEM>>>(P);
    round_copy<<<512, 256>>>(scr + S_UG1, scr + S_RUG1, 524288);

    P.j[0] = GJob{iu, scr + S_RUG1, nullptr, scr + S_IG1, IDIM, 8192};
    P.j[1] = P.j[0];
    gemm_cp<<<dim3(32, 16, 1), 128, GEMM_SMEM>>>(P);
    round_copy<<<256, 256>>>(scr + S_IG1, scr + S_RIG1, 262144);

    P.j[0] = GJob{ui, scr + S_RIG1, nullptr, scr + S_UG2, UDIM, 4096};
    P.j[1] = P.j[0];
    gemm_cp<<<dim3(64, 8, 1), 128, GEMM_SMEM>>>(P);
    softmax_kernel<<<1024, 256>>>(scr + S_UG2, scr + S_RUG2, UDIM);

    P.j[0] = GJob{iu, scr + S_RUG2, nullptr, scr + S_IG2, IDIM, 8192};
    P.j[1] = P.j[0];
    gemm_cp<<<dim3(32, 16, 1), 128, GEMM_SMEM>>>(P);
    softmax_kernel<<<512, 256>>>(scr + S_IG2, nullptr, IDIM);

    // final combine
    epilogue_kernel<<<1024, 256>>>(scr + S_UG0, scr + S_UG1, scr + S_UG2,
                                   out + OFF_IUF, out + OFF_TUF,
                                   out + OFF_UG_A, out + OFF_UG_B, UDIM);
    epilogue_kernel<<<512, 256>>>(scr + S_IG0, scr + S_IG1, scr + S_IG2,
                                  out + OFF_IIF, out + OFF_TIF,
                                  out + OFF_IG_A, out + OFF_IG_B, IDIM);
}

// round 5
// speedup vs baseline: 2.8963x; 1.0450x over previous
#include <cuda_runtime.h>
#include <math.h>
#include <stdint.h>

// ===========================================================================
// MMSSL forward — tf32 mma.sync + cp.async, fused-launch edition.
//  - gemm_cp:  C[M,64]  += rna(A) @ B_r,  128 thr, 4 CTAs/SM, up to 6 jobs/launch
//  - gemm128: [C1|C2][M,128] += rna(A) @ [B1|B2]_r, 256 thr (ui/iu read once)
//  - batched RNA-round prep, split-K fp32 atomicAdd epilogues everywhere
// ===========================================================================

#define UDIM 8192
#define IDIM 4096

static constexpr float MODEL_CAT = 0.55f;
static constexpr float ID_CAT    = 0.36f;

// ---- output offsets (floats) ----
static constexpr size_t OFF_UG_A  = 0;
static constexpr size_t OFF_IG_A  = 524288;
static constexpr size_t OFF_IIF   = 786432;
static constexpr size_t OFF_TIF   = 1048576;
static constexpr size_t OFF_IUF   = 1310720;
static constexpr size_t OFF_TUF   = 1835008;
static constexpr size_t OFF_UG_B  = 2359296;
static constexpr size_t OFF_IG_B  = 2883584;
static constexpr size_t OFF_IUID  = 3145728;
static constexpr size_t OFF_TUID  = 3670016;

// ---- scratch (floats); [0, S_ZERO_END) is atomic-accumulated, zeroed ----
static constexpr size_t S_IMGF  = 0;         // img_f [I,64]  (TXTF contiguous)
static constexpr size_t S_TXTF  = 262144;
static constexpr size_t S_IIID  = 524288;
static constexpr size_t S_TIID  = 786432;
static constexpr size_t S_UG1   = 1048576;
static constexpr size_t S_UG2   = 1572864;
static constexpr size_t S_IG1   = 2097152;
static constexpr size_t S_IG2   = 2359296;
static constexpr size_t S_ZERO_END = 2621440;
static constexpr size_t S_UG0   = 2621440;
static constexpr size_t S_IG0   = 3145728;
// rounded-B buffers
static constexpr size_t S_RWIMG = 3407872;   // 262144
static constexpr size_t S_RWTXT = 3670016;   // 65536
static constexpr size_t S_RIID  = 3735552;   // 262144
static constexpr size_t S_RUID  = 3997696;   // 524288
static constexpr size_t S_RB3   = 4521984;   // 2x524288 (IUF_r | TUF_r contig)
static constexpr size_t S_RIG0  = 5570560;   // 262144
static constexpr size_t S_RUG1  = 5832704;   // 524288
static constexpr size_t S_RIG1  = 6356992;   // 262144
static constexpr size_t S_RUG2  = 6881280;   // 524288
static constexpr size_t S_TOTAL = 7405568;

__device__ float g_scratch[S_TOTAL];

// ===========================================================================
__device__ __forceinline__ float rna_tf32(float x) {
    float r;
    asm("cvt.rna.tf32.f32 %0, %1;" : "=f"(r) : "f"(x));
    return r;
}
__device__ __forceinline__ uint32_t s2u(const void* p) {
    uint32_t a;
    asm("{ .reg .u64 t; cvta.to.shared.u64 t, %1; cvt.u32.u64 %0, t; }"
        : "=r"(a) : "l"(p));
    return a;
}
__device__ __forceinline__ void cp16(uint32_t s, const void* g) {
    asm volatile("cp.async.cg.shared.global [%0], [%1], 16;"
                 :: "r"(s), "l"(g) : "memory");
}
__device__ __forceinline__ float lds_f(uint32_t a) {
    float v;
    asm volatile("ld.shared.f32 %0, [%1];" : "=f"(v) : "r"(a));
    return v;
}
__device__ __forceinline__ void mma8(float* d,
                                     uint32_t a0, uint32_t a1, uint32_t a2, uint32_t a3,
                                     uint32_t b0, uint32_t b1) {
    asm volatile(
        "mma.sync.aligned.m16n8k8.row.col.f32.tf32.tf32.f32 "
        "{%0,%1,%2,%3}, {%4,%5,%6,%7}, {%8,%9}, {%0,%1,%2,%3};\n"
        : "+f"(d[0]), "+f"(d[1]), "+f"(d[2]), "+f"(d[3])
        : "r"(a0), "r"(a1), "r"(a2), "r"(a3), "r"(b0), "r"(b1));
}

// ===========================================================================
struct GJob {
    const float* A;
    const float* B;
    const float* bias;
    float* C;
    int M;
    int K;
};
struct GJobs6 { GJob j[6]; };

// ---------------- N=64 GEMM (128 threads, 4 CTAs/SM) ----------------------
static constexpr uint32_t ABUF_B  = 128u * 144u;          // 18432
static constexpr uint32_t BBUF_B  = 32u * 288u;           // 9216
static constexpr uint32_t STAGE_B = ABUF_B + BBUF_B;      // 27648
static constexpr uint32_t GEMM_SMEM = 2u * STAGE_B;       // 55296

__global__ __launch_bounds__(128, 4) void gemm_cp(GJobs6 P)
{
    extern __shared__ char sm[];
    const GJob jb = P.j[blockIdx.z];
    const int mb = blockIdx.x * 128;
    if (mb >= jb.M) return;
    const int K = jb.K;
    const int chunk = K / (int)gridDim.y;
    const int k0 = (int)blockIdx.y * chunk;
    const int nt = chunk >> 5;

    const int tid  = threadIdx.x;
    const int lane = tid & 31;
    const int wid  = tid >> 5;
    const int gid  = lane >> 2;
    const int tig  = lane & 3;
    const int wm   = (wid & 1) * 64;
    const int wn   = (wid >> 1) * 32;

    const uint32_t sb = s2u(sm);
    const float* __restrict__ Ag = jb.A + (size_t)mb * K + k0;
    const float* __restrict__ Bg = jb.B + (size_t)k0 * 64;

    float acc[4][4][4];
#pragma unroll
    for (int m = 0; m < 4; m++)
#pragma unroll
        for (int j = 0; j < 4; j++)
#pragma unroll
            for (int c = 0; c < 4; c++) acc[m][j][c] = 0.f;

    auto LOAD = [&](int t, int buf) {
        const uint32_t ab = sb + (uint32_t)buf * STAGE_B;
        const uint32_t bb = ab + ABUF_B;
        const float* At = Ag + t * 32;
        const float* Bt = Bg + (size_t)t * 32 * 64;
#pragma unroll
        for (int i = 0; i < 8; i++) {
            int c = i * 128 + tid;
            int row = c >> 3, seg = c & 7;
            cp16(ab + (uint32_t)(row * 144 + seg * 16),
                 At + (size_t)row * K + seg * 4);
        }
#pragma unroll
        for (int i = 0; i < 4; i++) {
            int c = i * 128 + tid;
            int k = c >> 4, seg = c & 15;
            cp16(bb + (uint32_t)(k * 288 + seg * 16),
                 Bt + (size_t)k * 64 + seg * 4);
        }
        asm volatile("cp.async.commit_group;" ::: "memory");
    };

    auto COMP = [&](int buf) {
        const uint32_t ab = sb + (uint32_t)buf * STAGE_B;
        const uint32_t bb = ab + ABUF_B;
#pragma unroll
        for (int ks = 0; ks < 4; ks++) {
            uint32_t a0[4], a1[4], a2[4], a3[4];
            const int k = ks * 8 + tig;
#pragma unroll
            for (int mt = 0; mt < 4; mt++) {
                int row = wm + mt * 16 + gid;
                float x0 = lds_f(ab + (uint32_t)((row * 36 + k) << 2));
                float x1 = lds_f(ab + (uint32_t)(((row + 8) * 36 + k) << 2));
                float x2 = lds_f(ab + (uint32_t)((row * 36 + k + 4) << 2));
                float x3 = lds_f(ab + (uint32_t)(((row + 8) * 36 + k + 4) << 2));
                a0[mt] = __float_as_uint(rna_tf32(x0));
                a1[mt] = __float_as_uint(rna_tf32(x1));
                a2[mt] = __float_as_uint(rna_tf32(x2));
                a3[mt] = __float_as_uint(rna_tf32(x3));
            }
#pragma unroll
            for (int j = 0; j < 4; j++) {
                int col = wn + j * 8 + gid;
                uint32_t b0 = __float_as_uint(
                    lds_f(bb + (uint32_t)(((ks * 8 + tig) * 72 + col) << 2)));
                uint32_t b1 = __float_as_uint(
                    lds_f(bb + (uint32_t)(((ks * 8 + tig + 4) * 72 + col) << 2)));
#pragma unroll
                for (int mt = 0; mt < 4; mt++)
                    mma8(acc[mt][j], a0[mt], a1[mt], a2[mt], a3[mt], b0, b1);
            }
        }
    };

    LOAD(0, 0);
    for (int t = 0; t < nt; t++) {
        const int buf = t & 1;
        if (t + 1 < nt) {
            LOAD(t + 1, buf ^ 1);
            asm volatile("cp.async.wait_group 1;" ::: "memory");
        } else {
            asm volatile("cp.async.wait_group 0;" ::: "memory");
        }
        __syncthreads();
        COMP(buf);
        __syncthreads();
    }

    const bool addb = (blockIdx.y == 0) && (jb.bias != nullptr);
#pragma unroll
    for (int mt = 0; mt < 4; mt++) {
#pragma unroll
        for (int j = 0; j < 4; j++) {
            int row = mb + wm + mt * 16 + gid;
            int col = wn + j * 8 + 2 * tig;
            float b0 = addb ? jb.bias[col] : 0.f;
            float b1 = addb ? jb.bias[col + 1] : 0.f;
            atomicAdd(jb.C + (size_t)row * 64 + col,           acc[mt][j][0] + b0);
            atomicAdd(jb.C + (size_t)row * 64 + col + 1,       acc[mt][j][1] + b1);
            atomicAdd(jb.C + (size_t)(row + 8) * 64 + col,     acc[mt][j][2] + b0);
            atomicAdd(jb.C + (size_t)(row + 8) * 64 + col + 1, acc[mt][j][3] + b1);
        }
    }
}

// ---------------- N=128 GEMM (256 threads): A read once, two B/C -----------
// B1,B2 are separate [K,64] rounded buffers; C1,C2 separate [M,64] outputs.
struct G128 {
    const float* A;
    const float* B1;
    const float* B2;
    float* C1;
    float* C2;
    int M;
    int K;
};

static constexpr uint32_t B128_B   = 32u * 544u;            // [32][136] f32
static constexpr uint32_t STAGE128 = ABUF_B + B128_B;       // 35840
static constexpr uint32_t SMEM128  = 2u * STAGE128;         // 71680

__global__ __launch_bounds__(256, 2) void gemm128(G128 jb)
{
    extern __shared__ char sm[];
    const int mb = blockIdx.x * 128;
    const int K = jb.K;
    const int chunk = K / (int)gridDim.y;
    const int k0 = (int)blockIdx.y * chunk;
    const int nt = chunk >> 5;

    const int tid  = threadIdx.x;
    const int lane = tid & 31;
    const int wid  = tid >> 5;
    const int gid  = lane >> 2;
    const int tig  = lane & 3;
    const int wm   = (wid & 1) * 64;
    const int wn   = (wid >> 1) * 32;      // 0,32,64,96

    const uint32_t sb = s2u(sm);
    const float* __restrict__ Ag = jb.A + (size_t)mb * K + k0;
    const float* __restrict__ B1 = jb.B1 + (size_t)k0 * 64;
    const float* __restrict__ B2 = jb.B2 + (size_t)k0 * 64;

    float acc[4][4][4];
#pragma unroll
    for (int m = 0; m < 4; m++)
#pragma unroll
        for (int j = 0; j < 4; j++)
#pragma unroll
            for (int c = 0; c < 4; c++) acc[m][j][c] = 0.f;

    auto LOAD = [&](int t, int buf) {
        const uint32_t ab = sb + (uint32_t)buf * STAGE128;
        const uint32_t bb = ab + ABUF_B;
        const float* At = Ag + t * 32;
#pragma unroll
        for (int i = 0; i < 4; i++) {
            int c = i * 256 + tid;
            int row = c >> 3, seg = c & 7;
            cp16(ab + (uint32_t)(row * 144 + seg * 16),
                 At + (size_t)row * K + seg * 4);
        }
        // B: rows [32][136]; cols 0..63 from B1, 64..127 from B2
#pragma unroll
        for (int i = 0; i < 4; i++) {
            int c = i * 256 + tid;
            int k = c >> 5, seg = c & 31;       // seg*4 = col
            const float* src = (seg < 16)
                ? (B1 + ((size_t)t * 32 + k) * 64 + seg * 4)
                : (B2 + ((size_t)t * 32 + k) * 64 + (seg - 16) * 4);
            cp16(bb + (uint32_t)(k * 544 + seg * 16), src);
        }
        asm volatile("cp.async.commit_group;" ::: "memory");
    };

    auto COMP = [&](int buf) {
        const uint32_t ab = sb + (uint32_t)buf * STAGE128;
        const uint32_t bb = ab + ABUF_B;
#pragma unroll
        for (int ks = 0; ks < 4; ks++) {
            uint32_t a0[4], a1[4], a2[4], a3[4];
            const int k = ks * 8 + tig;
#pragma unroll
            for (int mt = 0; mt < 4; mt++) {
                int row = wm + mt * 16 + gid;
                float x0 = lds_f(ab + (uint32_t)((row * 36 + k) << 2));
                float x1 = lds_f(ab + (uint32_t)(((row + 8) * 36 + k) << 2));
                float x2 = lds_f(ab + (uint32_t)((row * 36 + k + 4) << 2));
                float x3 = lds_f(ab + (uint32_t)(((row + 8) * 36 + k + 4) << 2));
                a0[mt] = __float_as_uint(rna_tf32(x0));
                a1[mt] = __float_as_uint(rna_tf32(x1));
                a2[mt] = __float_as_uint(rna_tf32(x2));
                a3[mt] = __float_as_uint(rna_tf32(x3));
            }
#pragma unroll
            for (int j = 0; j < 4; j++) {
                int col = wn + j * 8 + gid;
                uint32_t b0 = __float_as_uint(
                    lds_f(bb + (uint32_t)(((ks * 8 + tig) * 136 + col) << 2)));
                uint32_t b1 = __float_as_uint(
                    lds_f(bb + (uint32_t)(((ks * 8 + tig + 4) * 136 + col) << 2)));
#pragma unroll
                for (int mt = 0; mt < 4; mt++)
                    mma8(acc[mt][j], a0[mt], a1[mt], a2[mt], a3[mt], b0, b1);
            }
        }
    };

    LOAD(0, 0);
    for (int t = 0; t < nt; t++) {
        const int buf = t & 1;
        if (t + 1 < nt) {
            LOAD(t + 1, buf ^ 1);
            asm volatile("cp.async.wait_group 1;" ::: "memory");
        } else {
            asm volatile("cp.async.wait_group 0;" ::: "memory");
        }
        __syncthreads();
        COMP(buf);
        __syncthreads();
    }

#pragma unroll
    for (int mt = 0; mt < 4; mt++) {
#pragma unroll
        for (int j = 0; j < 4; j++) {
            int row = mb + wm + mt * 16 + gid;
            int col = wn + j * 8 + 2 * tig;
            float* C = (col < 64) ? jb.C1 : jb.C2;
            int cc = col & 63;
            atomicAdd(C + (size_t)row * 64 + cc,           acc[mt][j][0]);
            atomicAdd(C + (size_t)row * 64 + cc + 1,       acc[mt][j][1]);
            atomicAdd(C + (size_t)(row + 8) * 64 + cc,     acc[mt][j][2]);
            atomicAdd(C + (size_t)(row + 8) * 64 + cc + 1, acc[mt][j][3]);
        }
    }
}

// ===========================================================================
// batched elementwise RNA round
// ===========================================================================
struct RJob { const float* s; float* d; int n; };
struct RJobs4 { RJob j[4]; };

__global__ __launch_bounds__(256) void round_batch(RJobs4 P)
{
    const RJob jb = P.j[blockIdx.z];
    int i = blockIdx.x * 256 + threadIdx.x;
    int stride = gridDim.x * 256;
    for (; i < jb.n; i += stride) jb.d[i] = rna_tf32(jb.s[i]);
}

// ===========================================================================
// MHSA over the 2-modality axis fused with mean/norm/id-add
// ===========================================================================
__global__ __launch_bounds__(256) void mhsa_kernel(
    const float* __restrict__ xi, const float* __restrict__ xt,
    const float* __restrict__ idemb,
    const float* __restrict__ wq, const float* __restrict__ wk,
    const float* __restrict__ wcat,
    float* __restrict__ outp, float* __restrict__ outr, int M)
{
    __shared__ float sx[8][2][64];
    __shared__ float sqk[8][4][64];
    __shared__ float satt[8][16];
    const int warp = threadIdx.x >> 5;
    const int lane = threadIdx.x & 31;
    const int gw = blockIdx.x * 8 + warp;
    const int nw = gridDim.x * 8;

    for (int n = gw; n < M; n += nw) {
        sx[warp][0][lane]      = xi[(size_t)n * 64 + lane];
        sx[warp][0][lane + 32] = xi[(size_t)n * 64 + lane + 32];
        sx[warp][1][lane]      = xt[(size_t)n * 64 + lane];
        sx[warp][1][lane + 32] = xt[(size_t)n * 64 + lane + 32];
        __syncwarp();

        float qi0=0,qi1=0,ki0=0,ki1=0,qt0=0,qt1=0,kt0=0,kt1=0;
        float pi[4][2] = {}, pt[4][2] = {};
#pragma unroll 4
        for (int k = 0; k < 64; k++) {
            float xik = sx[warp][0][k];
            float xtk = sx[warp][1][k];
            float wq0 = wq[k * 64 + lane],      wq1 = wq[k * 64 + lane + 32];
            float wk0 = wk[k * 64 + lane],      wk1 = wk[k * 64 + lane + 32];
            qi0 = fmaf(xik, wq0, qi0); qi1 = fmaf(xik, wq1, qi1);
            ki0 = fmaf(xik, wk0, ki0); ki1 = fmaf(xik, wk1, ki1);
            qt0 = fmaf(xtk, wq0, qt0); qt1 = fmaf(xtk, wq1, qt1);
            kt0 = fmaf(xtk, wk0, kt0); kt1 = fmaf(xtk, wk1, kt1);
#pragma unroll
            for (int h = 0; h < 4; h++) {
                float wc0 = wcat[(h * 64 + k) * 64 + lane];
                float wc1 = wcat[(h * 64 + k) * 64 + lane + 32];
                pi[h][0] = fmaf(xik, wc0, pi[h][0]);
                pi[h][1] = fmaf(xik, wc1, pi[h][1]);
                pt[h][0] = fmaf(xtk, wc0, pt[h][0]);
                pt[h][1] = fmaf(xtk, wc1, pt[h][1]);
            }
        }
        sqk[warp][0][lane] = qi0; sqk[warp][0][lane + 32] = qi1;
        sqk[warp][1][lane] = ki0; sqk[warp][1][lane + 32] = ki1;
        sqk[warp][2][lane] = qt0; sqk[warp][2][lane + 32] = qt1;
        sqk[warp][3][lane] = kt0; sqk[warp][3][lane + 32] = kt1;
        __syncwarp();

        {
            int cc = lane & 15;
            int h = cc >> 2, a = (cc >> 1) & 1, b = cc & 1;
            const float* qv = &sqk[warp][a * 2][h * 16];
            const float* kv = &sqk[warp][1 + b * 2][h * 16];
            float l = 0.f;
#pragma unroll
            for (int u = 0; u < 16; u++) l = fmaf(qv[u], kv[u], l);
            l *= 0.25f;
            float lo = __shfl_xor_sync(0xffffffffu, l, 1);
            float mm = fmaxf(l, lo);
            float e  = expf(l - mm);
            float eo = __shfl_xor_sync(0xffffffffu, e, 1);
            float att = e / (e + eo);
            if (lane < 16) satt[warp][lane] = att;
        }
        __syncwarp();

        float z0 = 0.f, z1 = 0.f;
#pragma unroll
        for (int h = 0; h < 4; h++) {
            float cih = 0.5f * (satt[warp][h * 4 + 0] + satt[warp][h * 4 + 2]);
            float cth = 0.5f * (satt[warp][h * 4 + 1] + satt[warp][h * 4 + 3]);
            z0 = fmaf(cih, pi[h][0], fmaf(cth, pt[h][0], z0));
            z1 = fmaf(cih, pi[h][1], fmaf(cth, pt[h][1], z1));
        }
        float ss = z0 * z0 + z1 * z1;
#pragma unroll
        for (int o = 16; o; o >>= 1) ss += __shfl_xor_sync(0xffffffffu, ss, o);
        float scale = ID_CAT / fmaxf(sqrtf(ss), 1e-12f);
        float r0 = idemb[(size_t)n * 64 + lane]      + z0 * scale;
        float r1 = idemb[(size_t)n * 64 + lane + 32] + z1 * scale;
        outp[(size_t)n * 64 + lane]      = r0;
        outp[(size_t)n * 64 + lane + 32] = r1;
        if (outr) {
            outr[(size_t)n * 64 + lane]      = rna_tf32(r0);
            outr[(size_t)n * 64 + lane + 32] = rna_tf32(r1);
        }
        __syncwarp();
    }
}

// row softmax; optional rounded copy
__global__ __launch_bounds__(256) void softmax_kernel(
    float* __restrict__ X, float* __restrict__ outr, int M)
{
    const int warp = threadIdx.x >> 5;
    const int lane = threadIdx.x & 31;
    const int gw = blockIdx.x * 8 + warp;
    const int nw = gridDim.x * 8;
    for (int n = gw; n < M; n += nw) {
        size_t i = (size_t)n * 64 + lane;
        float v0 = X[i], v1 = X[i + 32];
        float m = fmaxf(v0, v1);
#pragma unroll
        for (int o = 16; o; o >>= 1) m = fmaxf(m, __shfl_xor_sync(0xffffffffu, m, o));
        float e0 = expf(v0 - m), e1 = expf(v1 - m);
        float s = e0 + e1;
#pragma unroll
        for (int o = 16; o; o >>= 1) s += __shfl_xor_sync(0xffffffffu, s, o);
        float inv = 1.0f / s;
        float r0 = e0 * inv, r1 = e1 * inv;
        X[i] = r0;
        X[i + 32] = r1;
        if (outr) {
            outr[i] = rna_tf32(r0);
            outr[i + 32] = rna_tf32(r1);
        }
    }
}

__global__ __launch_bounds__(256) void epilogue_kernel(
    const float* __restrict__ g0, const float* __restrict__ g1,
    const float* __restrict__ g2,
    const float* __restrict__ fA, const float* __restrict__ fB,
    float* __restrict__ o1, float* __restrict__ o2, int M)
{
    const int warp = threadIdx.x >> 5;
    const int lane = threadIdx.x & 31;
    const int gw = blockIdx.x * 8 + warp;
    const int nw = gridDim.x * 8;
    for (int n = gw; n < M; n += nw) {
        size_t i = (size_t)n * 64 + lane;
        size_t i2 = i + 32;
        float m0 = (g0[i]  + g1[i]  + g2[i])  * (1.0f / 3.0f);
        float m1 = (g0[i2] + g1[i2] + g2[i2]) * (1.0f / 3.0f);
        float a0 = fA[i], a1 = fA[i2];
        float ssa = a0 * a0 + a1 * a1;
#pragma unroll
        for (int o = 16; o; o >>= 1) ssa += __shfl_xor_sync(0xffffffffu, ssa, o);
        float sA = MODEL_CAT / fmaxf(sqrtf(ssa), 1e-12f);
        float b0 = fB[i], b1 = fB[i2];
        float ssb = b0 * b0 + b1 * b1;
#pragma unroll
        for (int o = 16; o; o >>= 1) ssb += __shfl_xor_sync(0xffffffffu, ssb, o);
        float sB = MODEL_CAT / fmaxf(sqrtf(ssb), 1e-12f);
        float r0 = m0 + a0 * sA + b0 * sB;
        float r1 = m1 + a1 * sA + b1 * sB;
        o1[i] = r0;  o1[i2] = r1;
        o2[i] = r0;  o2[i2] = r1;
    }
}

// ===========================================================================
extern "C" void kernel_launch(void* const* d_in, const int* in_sizes, int n_in,
                              void* d_out, int out_size)
{
    const float* ui      = (const float*)d_in[0];
    const float* iu      = (const float*)d_in[1];
    const float* img_ui  = (const float*)d_in[2];
    const float* img_iu  = (const float*)d_in[3];
    const float* txt_ui  = (const float*)d_in[4];
    const float* txt_iu  = (const float*)d_in[5];
    const float* imgF    = (const float*)d_in[6];
    const float* txtF    = (const float*)d_in[7];
    const float* W_img   = (const float*)d_in[8];
    const float* b_img   = (const float*)d_in[9];
    const float* W_txt   = (const float*)d_in[10];
    const float* b_txt   = (const float*)d_in[11];
    const float* uid     = (const float*)d_in[12];
    const float* iid     = (const float*)d_in[13];
    const float* w_q     = (const float*)d_in[14];
    const float* w_k     = (const float*)d_in[15];
    const float* w_cat   = (const float*)d_in[16];
    float* out = (float*)d_out;

    float* scr = nullptr;
    cudaGetSymbolAddress((void**)&scr, g_scratch);

    cudaFuncSetAttribute(gemm_cp, cudaFuncAttributeMaxDynamicSharedMemorySize,
                         (int)GEMM_SMEM);
    cudaFuncSetAttribute(gemm128, cudaFuncAttributeMaxDynamicSharedMemorySize,
                         (int)SMEM128);

    // zero atomic-accumulation targets (d_out is poisoned)
    cudaMemsetAsync(out, 0, (size_t)4194304 * sizeof(float));
    cudaMemsetAsync(scr, 0, S_ZERO_END * sizeof(float));

    // prep: round static B operands (one batched launch)
    RJobs4 R;
    R.j[0] = RJob{W_img, scr + S_RWIMG, 262144};
    R.j[1] = RJob{W_txt, scr + S_RWTXT, 65536};
    R.j[2] = RJob{iid,   scr + S_RIID,  262144};
    R.j[3] = RJob{uid,   scr + S_RUID,  524288};
    round_batch<<<dim3(128, 1, 4), 256>>>(R);

    // MEGA launch: G1 (projections) + G4a + G4b (id propagations), 6 jobs
    GJobs6 P;
    P.j[0] = GJob{imgF,   scr + S_RWIMG, b_img, scr + S_IMGF,   IDIM, 4096};
    P.j[1] = GJob{txtF,   scr + S_RWTXT, b_txt, scr + S_TXTF,   IDIM, 1024};
    P.j[2] = GJob{img_ui, scr + S_RIID, nullptr, out + OFF_IUID, UDIM, 4096};
    P.j[3] = GJob{txt_ui, scr + S_RIID, nullptr, out + OFF_TUID, UDIM, 4096};
    P.j[4] = GJob{img_iu, scr + S_RUID, nullptr, scr + S_IIID,   IDIM, 8192};
    P.j[5] = GJob{txt_iu, scr + S_RUID, nullptr, scr + S_TIID,   IDIM, 8192};
    gemm_cp<<<dim3(64, 4, 6), 128, GEMM_SMEM>>>(P);

    // round img_f|txt_f in place (contiguous)
    R.j[0] = RJob{scr + S_IMGF, scr + S_IMGF, 524288};
    round_batch<<<dim3(512, 1, 1), 256>>>(R);

    // G2: [imageUF|textUF] = ui @ [img_f|txt_f]  (ui read once)
    gemm128<<<dim3(64, 8, 1), 256, SMEM128>>>(
        G128{ui, scr + S_IMGF, scr + S_TXTF, out + OFF_IUF, out + OFF_TUF,
             UDIM, 4096});

    // rounded copies of UF for G3's B (contiguous in out)
    R.j[0] = RJob{out + OFF_IUF, scr + S_RB3, 1048576};
    round_batch<<<dim3(512, 1, 1), 256>>>(R);

    // G3: [imageIF|textIF] = iu @ [imageUF|textUF]  (iu read once)
    gemm128<<<dim3(32, 16, 1), 256, SMEM128>>>(
        G128{iu, scr + S_RB3, scr + S_RB3 + 524288, out + OFF_IIF, out + OFF_TIF,
             IDIM, 8192});

    // MHSA -> u_g0, i_g0 (i_g0 also emitted rounded for loop1 B)
    mhsa_kernel<<<1024, 256>>>(out + OFF_IUID, out + OFF_TUID, uid,
                               w_q, w_k, w_cat, scr + S_UG0, nullptr, UDIM);
    mhsa_kernel<<<512, 256>>>(scr + S_IIID, scr + S_TIID, iid,
                              w_q, w_k, w_cat, scr + S_IG0, scr + S_RIG0, IDIM);

    // propagation loop (N_UI = 2)
    P.j[0] = GJob{ui, scr + S_RIG0, nullptr, scr + S_UG1, UDIM, 4096};
    gemm_cp<<<dim3(64, 8, 1), 128, GEMM_SMEM>>>(P);
    R.j[0] = RJob{scr + S_UG1, scr + S_RUG1, 524288};
    round_batch<<<dim3(512, 1, 1), 256>>>(R);

    P.j[0] = GJob{iu, scr + S_RUG1, nullptr, scr + S_IG1, IDIM, 8192};
    gemm_cp<<<dim3(32, 16, 1), 128, GEMM_SMEM>>>(P);
    R.j[0] = RJob{scr + S_IG1, scr + S_RIG1, 262144};
    round_batch<<<dim3(256, 1, 1), 256>>>(R);

    P.j[0] = GJob{ui, scr + S_RIG1, nullptr, scr + S_UG2, UDIM, 4096};
    gemm_cp<<<dim3(64, 8, 1), 128, GEMM_SMEM>>>(P);
    softmax_kernel<<<1024, 256>>>(scr + S_UG2, scr + S_RUG2, UDIM);

    P.j[0] = GJob{iu, scr + S_RUG2, nullptr, scr + S_IG2, IDIM, 8192};
    gemm_cp<<<dim3(32, 16, 1), 128, GEMM_SMEM>>>(P);
    softmax_kernel<<<512, 256>>>(scr + S_IG2, nullptr, IDIM);

    // final combine
    epilogue_kernel<<<1024, 256>>>(scr + S_UG0, scr + S_UG1, scr + S_UG2,
                                   out + OFF_IUF, out + OFF_TUF,
                                   out + OFF_UG_A, out + OFF_UG_B, UDIM);
    epilogue_kernel<<<512, 256>>>(scr + S_IG0, scr + S_IG1, scr + S_IG2,
                                  out + OFF_IIF, out + OFF_TIF,
                                  out + OFF_IG_A, out + OFF_IG_B, IDIM);
}